// round 2
// baseline (speedup 1.0000x reference)
#include <cuda_runtime.h>
#include <cstdint>

#define NB 8
#define NA 49104
#define NC 90
#define IMGF 512.0f
#define SCORE_THR 0.2f
#define THR_BITS 0x3E4CCCCDu   /* bits of 0.2f; valid <=> bits > THR_BITS */
#define IOU_THR 0.2f
#define K_PRE 1000
#define K_OUT 100
#define NROW (NB * NA)

// ---------------- scratch ----------------
__device__ float g_maxs[NROW];
__device__ unsigned char g_cls[NROW];

// ---------------- K1: warp-per-row max/argmax, coalesced ----------------
#define RPW 4
__global__ void k_maxarg(const float* __restrict__ cls) {
    const int warp = (blockIdx.x * blockDim.x + threadIdx.x) >> 5;
    const int lane = threadIdx.x & 31;
    int row0 = warp * RPW;
#pragma unroll
    for (int r = 0; r < RPW; r++) {
        int row = row0 + r;
        const float2* p = reinterpret_cast<const float2*>(cls + (size_t)row * NC);
        float2 a = p[lane];                       // elements 2*lane, 2*lane+1
        unsigned long long key;
        {
            unsigned long long ka = ((unsigned long long)__float_as_uint(a.x) << 32) | (unsigned)(89 - 2 * lane);
            unsigned long long kb = ((unsigned long long)__float_as_uint(a.y) << 32) | (unsigned)(88 - 2 * lane);
            key = ka > kb ? ka : kb;
        }
        if (lane < 13) {                          // float2 indices 32..44 => elements 64..89
            float2 bq = p[lane + 32];
            int e = 64 + 2 * lane;
            unsigned long long ka = ((unsigned long long)__float_as_uint(bq.x) << 32) | (unsigned)(89 - e);
            unsigned long long kb = ((unsigned long long)__float_as_uint(bq.y) << 32) | (unsigned)(88 - e);
            unsigned long long m = ka > kb ? ka : kb;
            if (m > key) key = m;
        }
#pragma unroll
        for (int off = 16; off; off >>= 1) {
            unsigned long long o = __shfl_xor_sync(0xffffffffu, key, off);
            if (o > key) key = o;
        }
        if (lane == 0) {
            g_maxs[row] = __uint_as_float((unsigned)(key >> 32));
            g_cls[row] = (unsigned char)(89 - (int)(key & 0xFF));
        }
    }
}

// ---------------- K2: fused radix top-K + decode + NMS + output ----------------
__global__ void __launch_bounds__(1024, 1)
k_select_nms(const float* __restrict__ loc,
             const float* __restrict__ anchors,
             float* __restrict__ out) {
    const int b = blockIdx.x;
    const int tid = threadIdx.x;
    const int lane = tid & 31;
    const int NT = 1024;
    const float4* sc4 = reinterpret_cast<const float4*>(g_maxs + (size_t)b * NA);
    const int N4 = NA / 4;                         // 12276
    const int N4pad = ((N4 + NT - 1) / NT) * NT;   // 12288

    __shared__ int hist[256];
    __shared__ int s_valid, s_krem, s_cnt, s_nk;
    __shared__ unsigned s_prefix;
    __shared__ unsigned long long buf[2048];
    __shared__ float4 sbox[K_PRE];
    __shared__ float sval[K_PRE];
    __shared__ int scls[K_PRE];
    __shared__ float4 kbox[K_OUT];
    __shared__ float karea[K_OUT];
    __shared__ int kcls[K_OUT];
    __shared__ short kept[K_OUT];

    if (tid == 0) { s_valid = 0; s_cnt = 0; s_nk = 0; s_prefix = 0; }
    __syncthreads();

    unsigned prefix = 0;
    int krem = 0, K = 0;

    // ---- 4-level radix select over float bits (exact Kth-largest threshold) ----
    for (int level = 0; level < 4; level++) {
        const int shift = 24 - 8 * level;
        if (tid < 256) hist[tid] = 0;
        __syncthreads();

        int myvalid = 0;
        for (int i = tid; i < N4pad; i += NT) {
            float4 v = (i < N4) ? sc4[i] : make_float4(0.f, 0.f, 0.f, 0.f);
            unsigned kk[4] = { __float_as_uint(v.x), __float_as_uint(v.y),
                               __float_as_uint(v.z), __float_as_uint(v.w) };
#pragma unroll
            for (int c = 0; c < 4; c++) {
                unsigned key = (kk[c] > THR_BITS) ? kk[c] : 0u;
                if (level == 0) myvalid += (i < N4) && (key != 0u);
                bool m = (i < N4) &&
                         ((level == 0) || ((key >> (shift + 8)) == (prefix >> (shift + 8))));
                int bucket = m ? (int)((key >> shift) & 0xFF) : 300;
                unsigned grp = __match_any_sync(0xffffffffu, bucket);
                if (lane == (__ffs(grp) - 1) && bucket < 256)
                    atomicAdd(&hist[bucket], __popc(grp));
            }
        }
        if (level == 0) {
#pragma unroll
            for (int off = 16; off; off >>= 1)
                myvalid += __shfl_xor_sync(0xffffffffu, myvalid, off);
            if (lane == 0 && myvalid) atomicAdd(&s_valid, myvalid);
        }
        __syncthreads();
        if (level == 0) { K = min(K_PRE, s_valid); krem = K; }

        // parallel bucket selection (warp 0: 8 bins/lane, descending)
        if (tid < 32) {
            int c[8]; int ssum = 0;
#pragma unroll
            for (int j = 0; j < 8; j++) { c[j] = hist[255 - lane * 8 - j]; ssum += c[j]; }
            int pre = ssum;
#pragma unroll
            for (int off = 1; off < 32; off <<= 1) {
                int t = __shfl_up_sync(0xffffffffu, pre, off);
                if (lane >= off) pre += t;
            }
            int cum = pre - ssum;   // count in strictly-higher bins
            int found = -1, above = 0;
#pragma unroll
            for (int j = 0; j < 8; j++) {
                if (found < 0) {
                    if (cum + c[j] >= krem) { found = 255 - lane * 8 - j; above = cum; }
                    else cum += c[j];
                }
            }
            unsigned mm = __ballot_sync(0xffffffffu, found >= 0);
            if (mm && lane == (__ffs(mm) - 1)) {
                s_prefix = prefix | ((unsigned)found << shift);
                s_krem = krem - above;
            }
        }
        __syncthreads();
        prefix = s_prefix;
        krem = s_krem;
    }
    const unsigned T = prefix;   // exact Kth-largest score bits

    // ---- compaction: keys >= T, warp-aggregated ----
    if (K > 0) {
        for (int i = tid; i < N4pad; i += NT) {
            float4 v = (i < N4) ? sc4[i] : make_float4(0.f, 0.f, 0.f, 0.f);
            unsigned kk[4] = { __float_as_uint(v.x), __float_as_uint(v.y),
                               __float_as_uint(v.z), __float_as_uint(v.w) };
#pragma unroll
            for (int c = 0; c < 4; c++) {
                bool hit = (i < N4) && (kk[c] >= T);
                unsigned bal = __ballot_sync(0xffffffffu, hit);
                if (hit) {
                    int leader = __ffs(bal) - 1;
                    int pos = 0;
                    if (lane == leader) pos = atomicAdd(&s_cnt, __popc(bal));
                    pos = __shfl_sync(bal, pos, leader);
                    pos += __popc(bal & ((1u << lane) - 1));
                    int idx = i * 4 + c;
                    unsigned long long key =
                        ((unsigned long long)kk[c] << 32) |
                        ((unsigned long long)(0xFFFFu - (unsigned)idx) << 16) |
                        (unsigned long long)g_cls[(size_t)b * NA + idx];
                    if (pos < 2048) buf[pos] = key;
                }
            }
        }
    }
    __syncthreads();
    int n = min(s_cnt, 2048);
    for (int i = n + tid; i < 2048; i += NT) buf[i] = 0ULL;
    __syncthreads();

    // ---- bitonic sort, descending, 2048 keys ----
    for (int kk = 2; kk <= 2048; kk <<= 1) {
        for (int j = kk >> 1; j > 0; j >>= 1) {
            for (int i = tid; i < 2048; i += NT) {
                int ixj = i ^ j;
                if (ixj > i) {
                    bool descBlock = ((i & kk) == 0);
                    unsigned long long a = buf[i], c2 = buf[ixj];
                    bool sw = descBlock ? (a < c2) : (a > c2);
                    if (sw) { buf[i] = c2; buf[ixj] = a; }
                }
            }
            __syncthreads();
        }
    }

    // ---- decode top-K candidates ----
    for (int i = tid; i < K_PRE; i += NT) {
        if (i < K) {
            unsigned long long key = buf[i];
            unsigned idx = 0xFFFFu - (unsigned)((key >> 16) & 0xFFFFu);
            float score = __uint_as_float((unsigned)(key >> 32));
            float4 an = reinterpret_cast<const float4*>(anchors)[idx];      // y1,x1,y2,x2
            float4 lp = reinterpret_cast<const float4*>(loc)[(size_t)b * NA + idx]; // dy,dx,dh,dw
            float ya = (an.x + an.z) * 0.5f, xa = (an.y + an.w) * 0.5f;
            float ha = an.z - an.x, wa = an.w - an.y;
            float h = expf(lp.z) * ha;
            float w = expf(lp.w) * wa;
            float yc = lp.x * ha + ya;
            float xc = lp.y * wa + xa;
            float x1 = fminf(fmaxf(xc - 0.5f * w, 0.f), IMGF);
            float y1 = fminf(fmaxf(yc - 0.5f * h, 0.f), IMGF);
            float x2 = fminf(fmaxf(xc + 0.5f * w, 0.f), IMGF);
            float y2 = fminf(fmaxf(yc + 0.5f * h, 0.f), IMGF);
            sbox[i] = make_float4(x1, y1, x2, y2);
            sval[i] = score;
            scls[i] = (int)(key & 0xFFFFu);
        } else {
            sbox[i] = make_float4(0.f, 0.f, 0.f, 0.f);
            sval[i] = -1.0f;
            scls[i] = -1;
        }
    }
    __syncthreads();

    // ---- greedy NMS, warp 0 (early exit at K_OUT kept) ----
    if (tid < 32) {
        int nk = 0;
        for (int i = 0; i < K && nk < K_OUT; i++) {
            float v = sval[i];
            if (!(v > SCORE_THR)) continue;
            float4 bi = sbox[i];
            int ci = scls[i];
            float ai = (bi.z - bi.x) * (bi.w - bi.y);
            bool sup = false;
#pragma unroll
            for (int r = 0; r < 4; r++) {
                int slot = lane + (r << 5);
                if (slot < nk && kcls[slot] == ci) {
                    float4 bj = kbox[slot];
                    float xx1 = fmaxf(bi.x, bj.x), yy1 = fmaxf(bi.y, bj.y);
                    float xx2 = fminf(bi.z, bj.z), yy2 = fminf(bi.w, bj.w);
                    float in = fmaxf(xx2 - xx1, 0.f) * fmaxf(yy2 - yy1, 0.f);
                    float iou = in / (ai + karea[slot] - in + 1e-8f);
                    if (iou > IOU_THR) sup = true;
                }
            }
            if (__ballot_sync(0xffffffffu, sup) == 0u) {
                if (lane == 0) {
                    kbox[nk] = bi; karea[nk] = ai; kcls[nk] = ci; kept[nk] = (short)i;
                }
                __syncwarp();
                nk++;
            }
        }
        if (lane == 0) s_nk = nk;
    }
    __syncthreads();
    const int nk = s_nk;

    // ---- output: boxes [B,100,4] | scores [B,100] | labels [B,100] ----
    float* oboxes  = out + (size_t)b * K_OUT * 4;
    float* oscores = out + (size_t)NB * K_OUT * 4 + (size_t)b * K_OUT;
    float* olabels = out + (size_t)NB * K_OUT * 5 + (size_t)b * K_OUT;
    for (int s = tid; s < K_OUT; s += NT) {
        if (s < nk) {
            int i = kept[s];
            float4 bb = sbox[i];
            oboxes[s * 4 + 0] = bb.x;
            oboxes[s * 4 + 1] = bb.y;
            oboxes[s * 4 + 2] = bb.z;
            oboxes[s * 4 + 3] = bb.w;
            oscores[s] = sval[i];
            olabels[s] = (float)scls[i];
        } else {
            oboxes[s * 4 + 0] = 0.f;
            oboxes[s * 4 + 1] = 0.f;
            oboxes[s * 4 + 2] = 1.f;
            oboxes[s * 4 + 3] = 1.f;
            oscores[s] = 0.f;
            olabels[s] = -1.f;
        }
    }
}

// ---------------- launch ----------------
extern "C" void kernel_launch(void* const* d_in, const int* in_sizes, int n_in,
                              void* d_out, int out_size) {
    const float* cls     = (const float*)d_in[0];
    const float* loc     = (const float*)d_in[1];
    const float* anchors = (const float*)d_in[2];
    float* out = (float*)d_out;

    // NROW = 392832 rows; 8 warps/block * 4 rows/warp = 32 rows/block
    k_maxarg<<<NROW / 32, 256>>>(cls);
    k_select_nms<<<NB, 1024>>>(loc, anchors, out);
}

// round 3
// speedup vs baseline: 1.2586x; 1.2586x over previous
#include <cuda_runtime.h>
#include <cstdint>

#define NB 8
#define NA 49104
#define NC 90
#define IMGF 512.0f
#define SCORE_THR 0.2f
#define THR_BITS 0x3E4CCCCDu   /* bits of 0.2f; valid <=> bits > THR_BITS */
#define IOU_THR 0.2f
#define K_PRE 1000
#define K_OUT 100
#define NROW (NB * NA)
#define NBINS 10240
#define B0 0x7C999u            /* (THR_BITS >> 11) */
#define CAND_CAP 2048
#define ROWS_PB 64

typedef unsigned long long ull;

// ---------------- scratch ----------------
__device__ float g_maxs[NROW];
__device__ unsigned char g_cls[NROW];
__device__ int g_hist[NB * NBINS];
__device__ int g_cnt[NB];
__device__ unsigned g_thr[NB];
__device__ int g_K[NB];
__device__ ull g_cand[NB * CAND_CAP];

// ---------------- K0: zero scratch ----------------
__global__ void k_zero() {
    int t = blockIdx.x * blockDim.x + threadIdx.x;
    if (t < NB * NBINS) g_hist[t] = 0;
    if (t < NB) g_cnt[t] = 0;
}

// ---------------- K1: smem-staged max/argmax + histogram ----------------
__global__ void __launch_bounds__(256) k_maxarg(const float* __restrict__ cls) {
    __shared__ float s[ROWS_PB * NC];   // 23040 B
    const int blk = blockIdx.x;
    const int tid = threadIdx.x;

    const float4* src = reinterpret_cast<const float4*>(cls + (size_t)blk * ROWS_PB * NC);
    float4* dst = reinterpret_cast<float4*>(s);
#pragma unroll
    for (int i = 0; i < 6; i++) {
        int k = tid + i * 256;
        if (k < ROWS_PB * NC / 4) dst[k] = src[k];
    }
    __syncthreads();

    const int warp = tid >> 5, lane = tid & 31;
#pragma unroll
    for (int r = 0; r < 8; r++) {
        int row = warp * 8 + r;
        const float* p = s + row * NC;
        float v0 = p[lane];
        float v1 = p[lane + 32];
        ull k0 = ((ull)__float_as_uint(v0) << 32) | (unsigned)(89 - lane);
        ull k1 = ((ull)__float_as_uint(v1) << 32) | (unsigned)(57 - lane);
        ull key = k0 > k1 ? k0 : k1;
        if (lane < 26) {
            float v2 = p[lane + 64];
            ull k2 = ((ull)__float_as_uint(v2) << 32) | (unsigned)(25 - lane);
            if (k2 > key) key = k2;
        }
#pragma unroll
        for (int off = 16; off; off >>= 1) {
            ull o = __shfl_xor_sync(0xffffffffu, key, off);
            if (o > key) key = o;
        }
        if (lane == 0) {
            int grow = blk * ROWS_PB + row;
            unsigned bits = (unsigned)(key >> 32);
            g_maxs[grow] = __uint_as_float(bits);
            g_cls[grow] = (unsigned char)(89 - (int)(key & 0xFFu));
            if (bits > THR_BITS) {
                int b = grow / NA;
                int bin = (int)((bits >> 11) - B0);
                bin = min(bin, NBINS - 1);
                atomicAdd(&g_hist[b * NBINS + bin], 1);
            }
        }
    }
}

// ---------------- K2: per-image threshold bucket from histogram ----------------
__global__ void __launch_bounds__(1024) k_thresh() {
    const int b = blockIdx.x;
    const int tid = threadIdx.x;
    const int lane = tid & 31, w = tid >> 5;
    const int* h = g_hist + b * NBINS;

    int loc[10];
    int ssum = 0;
#pragma unroll
    for (int j = 0; j < 10; j++) {
        loc[j] = h[NBINS - 1 - (tid * 10 + j)];   // descending bins
        ssum += loc[j];
    }
    // block inclusive scan (thread order = descending bins)
    int ps = ssum;
#pragma unroll
    for (int off = 1; off < 32; off <<= 1) {
        int t = __shfl_up_sync(0xffffffffu, ps, off);
        if (lane >= off) ps += t;
    }
    __shared__ int wtot[32];
    if (lane == 31) wtot[w] = ps;
    __syncthreads();
    if (w == 0) {
        int v = wtot[lane];
#pragma unroll
        for (int off = 1; off < 32; off <<= 1) {
            int t = __shfl_up_sync(0xffffffffu, v, off);
            if (lane >= off) v += t;
        }
        wtot[lane] = v;   // inclusive warp prefix
    }
    __syncthreads();

    __shared__ unsigned s_thr;
    const int total = wtot[31];
    const int K = min(K_PRE, total);
    if (tid == 0) s_thr = 0xFFFFFFFFu;   // if K==0, nothing passes
    __syncthreads();

    if (K > 0) {
        int above = (ps - ssum) + (w > 0 ? wtot[w - 1] : 0);
        if (above < K && K <= above + ssum) {
            int cum = above;
#pragma unroll
            for (int j = 0; j < 10; j++) {
                if (cum + loc[j] >= K) {
                    s_thr = (unsigned)(B0 + (NBINS - 1 - (tid * 10 + j))) << 11;
                    break;
                }
                cum += loc[j];
            }
        }
    }
    __syncthreads();
    if (tid == 0) { g_thr[b] = s_thr; g_K[b] = K; }
}

// ---------------- K3: compact candidates >= threshold ----------------
__global__ void k_compact() {
    int t = blockIdx.x * blockDim.x + threadIdx.x;
    if (t >= NROW) return;
    int b = t / NA;
    int idx = t - b * NA;
    unsigned bits = __float_as_uint(g_maxs[t]);
    if (bits > THR_BITS && bits >= g_thr[b]) {
        int pos = atomicAdd(&g_cnt[b], 1);
        if (pos < CAND_CAP)
            g_cand[b * CAND_CAP + pos] =
                ((ull)bits << 32) | ((ull)(0xFFFFu - (unsigned)idx) << 16) |
                (ull)g_cls[t];
    }
}

// ---------------- K4: sort + decode + NMS + output ----------------
__global__ void __launch_bounds__(1024, 1)
k_nms(const float* __restrict__ loc,
      const float* __restrict__ anchors,
      float* __restrict__ out) {
    const int b = blockIdx.x;
    const int tid = threadIdx.x;
    const int lane = tid & 31;
    const int NT = 1024;

    __shared__ ull buf[CAND_CAP];
    __shared__ float4 sbox[K_PRE];
    __shared__ float sval[K_PRE];
    __shared__ int scls[K_PRE];
    __shared__ float4 kbox[K_OUT];
    __shared__ float karea[K_OUT];
    __shared__ int kcls[K_OUT];
    __shared__ short kept[K_OUT];
    __shared__ int s_nk;

    const int n = min(g_cnt[b], CAND_CAP);
    const int K = min(g_K[b], n);
    for (int i = tid; i < CAND_CAP; i += NT)
        buf[i] = (i < n) ? g_cand[b * CAND_CAP + i] : 0ULL;
    if (tid == 0) s_nk = 0;
    __syncthreads();

    // bitonic sort, descending, 2048 keys
    for (int kk = 2; kk <= CAND_CAP; kk <<= 1) {
        for (int j = kk >> 1; j > 0; j >>= 1) {
            for (int i = tid; i < CAND_CAP; i += NT) {
                int ixj = i ^ j;
                if (ixj > i) {
                    bool descBlock = ((i & kk) == 0);
                    ull a = buf[i], c2 = buf[ixj];
                    bool sw = descBlock ? (a < c2) : (a > c2);
                    if (sw) { buf[i] = c2; buf[ixj] = a; }
                }
            }
            __syncthreads();
        }
    }

    // decode top-K candidates
    for (int i = tid; i < K_PRE; i += NT) {
        if (i < K) {
            ull key = buf[i];
            unsigned idx = 0xFFFFu - (unsigned)((key >> 16) & 0xFFFFu);
            float score = __uint_as_float((unsigned)(key >> 32));
            float4 an = reinterpret_cast<const float4*>(anchors)[idx];           // y1,x1,y2,x2
            float4 lp = reinterpret_cast<const float4*>(loc)[(size_t)b * NA + idx]; // dy,dx,dh,dw
            float ya = (an.x + an.z) * 0.5f, xa = (an.y + an.w) * 0.5f;
            float ha = an.z - an.x, wa = an.w - an.y;
            float h = expf(lp.z) * ha;
            float w = expf(lp.w) * wa;
            float yc = lp.x * ha + ya;
            float xc = lp.y * wa + xa;
            float x1 = fminf(fmaxf(xc - 0.5f * w, 0.f), IMGF);
            float y1 = fminf(fmaxf(yc - 0.5f * h, 0.f), IMGF);
            float x2 = fminf(fmaxf(xc + 0.5f * w, 0.f), IMGF);
            float y2 = fminf(fmaxf(yc + 0.5f * h, 0.f), IMGF);
            sbox[i] = make_float4(x1, y1, x2, y2);
            sval[i] = score;
            scls[i] = (int)(key & 0xFFFFu);
        } else {
            sbox[i] = make_float4(0.f, 0.f, 0.f, 0.f);
            sval[i] = -1.0f;
            scls[i] = -1;
        }
    }
    __syncthreads();

    // greedy NMS, warp 0 (early exit at K_OUT kept)
    if (tid < 32) {
        int nk = 0;
        for (int i = 0; i < K && nk < K_OUT; i++) {
            float v = sval[i];
            if (!(v > SCORE_THR)) continue;
            float4 bi = sbox[i];
            int ci = scls[i];
            float ai = (bi.z - bi.x) * (bi.w - bi.y);
            bool sup = false;
#pragma unroll
            for (int r = 0; r < 4; r++) {
                int slot = lane + (r << 5);
                if (slot < nk && kcls[slot] == ci) {
                    float4 bj = kbox[slot];
                    float xx1 = fmaxf(bi.x, bj.x), yy1 = fmaxf(bi.y, bj.y);
                    float xx2 = fminf(bi.z, bj.z), yy2 = fminf(bi.w, bj.w);
                    float in = fmaxf(xx2 - xx1, 0.f) * fmaxf(yy2 - yy1, 0.f);
                    float iou = in / (ai + karea[slot] - in + 1e-8f);
                    if (iou > IOU_THR) sup = true;
                }
            }
            if (__ballot_sync(0xffffffffu, sup) == 0u) {
                if (lane == 0) {
                    kbox[nk] = bi; karea[nk] = ai; kcls[nk] = ci; kept[nk] = (short)i;
                }
                __syncwarp();
                nk++;
            }
        }
        if (lane == 0) s_nk = nk;
    }
    __syncthreads();
    const int nk = s_nk;

    // output: boxes [B,100,4] | scores [B,100] | labels [B,100]
    float* oboxes  = out + (size_t)b * K_OUT * 4;
    float* oscores = out + (size_t)NB * K_OUT * 4 + (size_t)b * K_OUT;
    float* olabels = out + (size_t)NB * K_OUT * 5 + (size_t)b * K_OUT;
    for (int s2 = tid; s2 < K_OUT; s2 += NT) {
        if (s2 < nk) {
            int i = kept[s2];
            float4 bb = sbox[i];
            oboxes[s2 * 4 + 0] = bb.x;
            oboxes[s2 * 4 + 1] = bb.y;
            oboxes[s2 * 4 + 2] = bb.z;
            oboxes[s2 * 4 + 3] = bb.w;
            oscores[s2] = sval[i];
            olabels[s2] = (float)scls[i];
        } else {
            oboxes[s2 * 4 + 0] = 0.f;
            oboxes[s2 * 4 + 1] = 0.f;
            oboxes[s2 * 4 + 2] = 1.f;
            oboxes[s2 * 4 + 3] = 1.f;
            oscores[s2] = 0.f;
            olabels[s2] = -1.f;
        }
    }
}

// ---------------- launch ----------------
extern "C" void kernel_launch(void* const* d_in, const int* in_sizes, int n_in,
                              void* d_out, int out_size) {
    const float* cls     = (const float*)d_in[0];
    const float* loc     = (const float*)d_in[1];
    const float* anchors = (const float*)d_in[2];
    float* out = (float*)d_out;

    k_zero<<<(NB * NBINS + 1023) / 1024, 1024>>>();
    k_maxarg<<<NROW / ROWS_PB, 256>>>(cls);           // 6138 blocks
    k_thresh<<<NB, 1024>>>();
    k_compact<<<(NROW + 255) / 256, 256>>>();
    k_nms<<<NB, 1024>>>(loc, anchors, out);
}